// round 6
// baseline (speedup 1.0000x reference)
#include <cuda_runtime.h>
#include <cuda_bf16.h>

// Trilinear scatter-add (Gridding).
// L2-resident chunked zero+scatter pipeline + vector reductions.
//
// Bottleneck (fitted R1-R3): L2 atomic-ALU op rate, ~2.5/3.1/4.5 LTS-cyc per
// scalar/v2/v4 red. Encoding (v2 / padded-v4 / 2x scalar by bz%4) is
// op-optimal under the 16B-window constraint -> ~5 ops/pt.
// This round: 16 chunks (halve exposed pipeline fill), 2 points/thread with
// front-batched loads, streaming (__ldcs) point loads so point data doesn't
// evict the L2-resident zeroed chunk. (evict_first on scalar ld is illegal
// on this ptxas -> use ld.global.cs instead.)
//
// All shape parameters derived on-device from scale/out_size.

__device__ __forceinline__ void get_dims(const int* __restrict__ scale_p,
                                         int out_size, int npts,
                                         int& s, int& G, int& G2, int& G3,
                                         int& B, int& N) {
    const int scale = *scale_p;
    s = scale >> 1;
    G = 2 * s;
    G2 = G * G;
    G3 = G2 * G;
    B = out_size / G3;
    N = npts / B;
}

__device__ __forceinline__ void red2(float* p, float a, float b) {
    asm volatile("red.global.add.v2.f32 [%0], {%1, %2};"
                 :: "l"(p), "f"(a), "f"(b) : "memory");
}

__device__ __forceinline__ void red4(float* p, float a, float b, float c, float d) {
    asm volatile("red.global.add.v4.f32 [%0], {%1, %2, %3, %4};"
                 :: "l"(p), "f"(a), "f"(b), "f"(c), "f"(d) : "memory");
}

// Zero batches [c*B/C, (c+1)*B/C) of the output with float4 stores.
__global__ void gridding_zero_chunk(float* __restrict__ out,
                                    const int* __restrict__ scale_p,
                                    int out_size, int npts, int c, int C) {
    int s, G, G2, G3, B, N;
    get_dims(scale_p, out_size, npts, s, G, G2, G3, B, N);

    const int b0 = (int)((long long)c * B / C);
    const int b1 = (int)((long long)(c + 1) * B / C);
    const size_t lo4 = (size_t)b0 * G3 / 4;   // G even -> G3 % 4 == 0
    const size_t hi4 = (size_t)b1 * G3 / 4;

    float4* o4 = reinterpret_cast<float4*>(out);
    const float4 z = make_float4(0.f, 0.f, 0.f, 0.f);
    const size_t stride = (size_t)gridDim.x * blockDim.x;
    for (size_t i = lo4 + (size_t)blockIdx.x * blockDim.x + threadIdx.x;
         i < hi4; i += stride) {
        o4[i] = z;
    }
}

// One point's 8-corner reduction.
__device__ __forceinline__ void scatter_point(float px, float py, float pz,
                                              int b, int s, int G, int G2,
                                              int G3, float* __restrict__ out) {
    const float m = (((px + py) + pz) != 0.0f) ? 1.0f : 0.0f;

    const float lx = floorf(px);
    const float ly = floorf(py);
    const float lz = floorf(pz);
    const float fx = px - lx;
    const float fy = py - ly;
    const float fz = pz - lz;

    const int bx = (int)lx + s;
    const int by = (int)ly + s;
    const int bz = (int)lz + s;

    const float wx0 = (1.0f - fx) * m;
    const float wx1 = fx * m;
    const float wy0 = 1.0f - fy;
    const float wy1 = fy;
    const float wz0 = 1.0f - fz;
    const float wz1 = fz;

    const float w00 = wx0 * wy0;
    const float w01 = wx0 * wy1;
    const float w10 = wx1 * wy0;
    const float w11 = wx1 * wy1;

    const float a0 = w00 * wz0, c0 = w00 * wz1;
    const float a1 = w01 * wz0, c1 = w01 * wz1;
    const float a2 = w10 * wz0, c2 = w10 * wz1;
    const float a3 = w11 * wz0, c3 = w11 * wz1;

    float* p0 = out + (size_t)b * G3 + ((size_t)bx * G + by) * G + bz;
    float* p1 = p0 + G;
    float* p2 = p0 + G2;
    float* p3 = p2 + G;

    const int off = bz & 3;
    if (off == 3) {
        atomicAdd(p0, a0); atomicAdd(p0 + 1, c0);
        atomicAdd(p1, a1); atomicAdd(p1 + 1, c1);
        atomicAdd(p2, a2); atomicAdd(p2 + 1, c2);
        atomicAdd(p3, a3); atomicAdd(p3 + 1, c3);
    } else if (off == 1) {
        red4(p0 - 1, 0.f, a0, c0, 0.f);
        red4(p1 - 1, 0.f, a1, c1, 0.f);
        red4(p2 - 1, 0.f, a2, c2, 0.f);
        red4(p3 - 1, 0.f, a3, c3, 0.f);
    } else {
        red2(p0, a0, c0);
        red2(p1, a1, c1);
        red2(p2, a2, c2);
        red2(p3, a3, c3);
    }
}

// Scatter the points of batches [c*B/C, (c+1)*B/C); 2 points per thread.
__global__ void gridding_scatter_chunk(const float* __restrict__ pts,
                                       const int* __restrict__ scale_p,
                                       float* __restrict__ out,
                                       int npts, int out_size, int c, int C) {
    int s, G, G2, G3, B, N;
    get_dims(scale_p, out_size, npts, s, G, G2, G3, B, N);

    const int b0 = (int)((long long)c * B / C);
    const int b1 = (int)((long long)(c + 1) * B / C);
    const int i_lo = b0 * N;
    const int i_hi = b1 * N;
    const int cnt = i_hi - i_lo;
    const int half = cnt >> 1;

    const float fs = (float)s;
    const int stride = gridDim.x * blockDim.x;

    for (int t = blockIdx.x * blockDim.x + threadIdx.x; t < half; t += stride) {
        const int i = i_lo + t;
        const int j = i + half;

        // Front-batch both points' loads (MLP); streaming hint keeps point
        // data from evicting the L2-resident zeroed output chunk.
        const float ax = __ldcs(pts + 3 * i + 0) * fs;
        const float ay = __ldcs(pts + 3 * i + 1) * fs;
        const float az = __ldcs(pts + 3 * i + 2) * fs;
        const float bx = __ldcs(pts + 3 * j + 0) * fs;
        const float by = __ldcs(pts + 3 * j + 1) * fs;
        const float bz = __ldcs(pts + 3 * j + 2) * fs;

        const int ba = b0 + (i - i_lo) / N;
        const int bb = b0 + (j - i_lo) / N;

        scatter_point(ax, ay, az, ba, s, G, G2, G3, out);
        scatter_point(bx, by, bz, bb, s, G, G2, G3, out);
    }
    // Odd leftover point (cnt odd) handled by thread 0 of block 0.
    if ((cnt & 1) && blockIdx.x == 0 && threadIdx.x == 0) {
        const int i = i_hi - 1;
        const float ax = __ldcs(pts + 3 * i + 0) * fs;
        const float ay = __ldcs(pts + 3 * i + 1) * fs;
        const float az = __ldcs(pts + 3 * i + 2) * fs;
        scatter_point(ax, ay, az, b0 + (i - i_lo) / N, s, G, G2, G3, out);
    }
}

static const int kChunks = 16;

extern "C" void kernel_launch(void* const* d_in, const int* in_sizes, int n_in,
                              void* d_out, int out_size) {
    const float* pts = (const float*)d_in[0];
    const int* scale_p = (const int*)d_in[1];
    float* out = (float*)d_out;

    const int npts = in_sizes[0] / 3;

    // One-time creation of helper streams + events (no device memory).
    static cudaStream_t sZ = nullptr;   // zeroing stream
    static cudaStream_t sS = nullptr;   // second scatter stream (odd chunks)
    static cudaEvent_t evFork = nullptr;
    static cudaEvent_t evZ[kChunks];
    static cudaEvent_t evS[kChunks];
    if (sZ == nullptr) {
        cudaStreamCreateWithFlags(&sZ, cudaStreamNonBlocking);
        cudaStreamCreateWithFlags(&sS, cudaStreamNonBlocking);
        cudaEventCreateWithFlags(&evFork, cudaEventDisableTiming);
        for (int c = 0; c < kChunks; c++) {
            cudaEventCreateWithFlags(&evZ[c], cudaEventDisableTiming);
            cudaEventCreateWithFlags(&evS[c], cudaEventDisableTiming);
        }
    }

    const int threads = 256;
    int blocksZ = (out_size / kChunks / 4 + threads - 1) / threads;
    if (blocksZ > 2048) blocksZ = 2048;
    if (blocksZ < 1) blocksZ = 1;
    int blocksS = (npts / kChunks / 2 + threads - 1) / threads + 1;

    // Fork side streams off the capture stream.
    cudaEventRecord(evFork, 0);
    cudaStreamWaitEvent(sZ, evFork, 0);
    cudaStreamWaitEvent(sS, evFork, 0);

    for (int c = 0; c < kChunks; c++) {
        // Rate-limit zeros: keep at most ~4 chunks (~64MB) hot in L2.
        if (c >= 4) cudaStreamWaitEvent(sZ, evS[c - 4], 0);

        gridding_zero_chunk<<<blocksZ, threads, 0, sZ>>>(
            out, scale_p, out_size, npts, c, kChunks);
        cudaEventRecord(evZ[c], sZ);

        // Scatter chunk c once its zeros are in L2; alternate streams so
        // consecutive chunks' scatters overlap back-to-back.
        cudaStream_t st = (c & 1) ? sS : (cudaStream_t)0;
        cudaStreamWaitEvent(st, evZ[c], 0);
        gridding_scatter_chunk<<<blocksS, threads, 0, st>>>(
            pts, scale_p, out, npts, out_size, c, kChunks);
        cudaEventRecord(evS[c], st);
    }

    // Join everything back into the capture stream.
    cudaStreamWaitEvent(0, evS[kChunks - 1], 0);
}

// round 7
// speedup vs baseline: 1.2424x; 1.2424x over previous
#include <cuda_runtime.h>
#include <cuda_bf16.h>

// Trilinear scatter-add (Gridding).
// L2-resident chunked zero+scatter pipeline + vector reductions.
//
// Locked-in findings (R1-R5):
//  - Total time == sum of isolated scatter-kernel times (fills hide across
//    graph replays; extra stream concurrency is neutral) -> only scatter
//    efficiency matters, at chunk sizes big enough to fill the chip.
//  - L2 red-op cost units: scalar 1.0 / v2 1.1 / v4 1.6. The bz%4-based
//    encoding (v2 / padded-v4 / 2x scalar) is optimal at ~5.8 units/pt.
//  - 8 chunks, 1 point/thread, 256-thr blocks is the efficient operating
//    point (16 chunks / 2 pts/thread regressed 28%).
//
// All shape parameters derived on-device from scale/out_size.

__device__ __forceinline__ void get_dims(const int* __restrict__ scale_p,
                                         int out_size, int npts,
                                         int& s, int& G, int& G2, int& G3,
                                         int& B, int& N) {
    const int scale = *scale_p;
    s = scale >> 1;
    G = 2 * s;
    G2 = G * G;
    G3 = G2 * G;
    B = out_size / G3;
    N = npts / B;
}

__device__ __forceinline__ void red2(float* p, float a, float b) {
    asm volatile("red.global.add.v2.f32 [%0], {%1, %2};"
                 :: "l"(p), "f"(a), "f"(b) : "memory");
}

__device__ __forceinline__ void red4(float* p, float a, float b, float c, float d) {
    asm volatile("red.global.add.v4.f32 [%0], {%1, %2, %3, %4};"
                 :: "l"(p), "f"(a), "f"(b), "f"(c), "f"(d) : "memory");
}

// Zero batches [c*B/C, (c+1)*B/C) of the output with float4 stores.
__global__ void gridding_zero_chunk(float* __restrict__ out,
                                    const int* __restrict__ scale_p,
                                    int out_size, int npts, int c, int C) {
    int s, G, G2, G3, B, N;
    get_dims(scale_p, out_size, npts, s, G, G2, G3, B, N);

    const int b0 = (int)((long long)c * B / C);
    const int b1 = (int)((long long)(c + 1) * B / C);
    const size_t lo4 = (size_t)b0 * G3 / 4;   // G even -> G3 % 4 == 0
    const size_t hi4 = (size_t)b1 * G3 / 4;

    float4* o4 = reinterpret_cast<float4*>(out);
    const float4 z = make_float4(0.f, 0.f, 0.f, 0.f);
    const size_t stride = (size_t)gridDim.x * blockDim.x;
    for (size_t i = lo4 + (size_t)blockIdx.x * blockDim.x + threadIdx.x;
         i < hi4; i += stride) {
        o4[i] = z;
    }
}

// Scatter the points of batches [c*B/C, (c+1)*B/C); one point per thread.
__global__ void gridding_scatter_chunk(const float* __restrict__ pts,
                                       const int* __restrict__ scale_p,
                                       float* __restrict__ out,
                                       int npts, int out_size, int c, int C) {
    int s, G, G2, G3, B, N;
    get_dims(scale_p, out_size, npts, s, G, G2, G3, B, N);

    const int b0 = (int)((long long)c * B / C);
    const int b1 = (int)((long long)(c + 1) * B / C);
    const int i_lo = b0 * N;
    const int i_hi = b1 * N;

    const int i = i_lo + blockIdx.x * blockDim.x + threadIdx.x;
    if (i >= i_hi) return;

    const float fs = (float)s;
    const int b = b0 + (i - i_lo) / N;

    const float px = pts[3 * i + 0] * fs;
    const float py = pts[3 * i + 1] * fs;
    const float pz = pts[3 * i + 2] * fs;

    // Reference drops points whose scaled coords sum to exactly 0.
    const float m = (((px + py) + pz) != 0.0f) ? 1.0f : 0.0f;

    const float lx = floorf(px);
    const float ly = floorf(py);
    const float lz = floorf(pz);
    const float fx = px - lx;
    const float fy = py - ly;
    const float fz = pz - lz;

    const int bx = (int)lx + s;
    const int by = (int)ly + s;
    const int bz = (int)lz + s;

    const float wx0 = (1.0f - fx) * m;
    const float wx1 = fx * m;
    const float wy0 = 1.0f - fy;
    const float wy1 = fy;
    const float wz0 = 1.0f - fz;
    const float wz1 = fz;

    const float w00 = wx0 * wy0;
    const float w01 = wx0 * wy1;
    const float w10 = wx1 * wy0;
    const float w11 = wx1 * wy1;

    const float a0 = w00 * wz0, c0 = w00 * wz1;
    const float a1 = w01 * wz0, c1 = w01 * wz1;
    const float a2 = w10 * wz0, c2 = w10 * wz1;
    const float a3 = w11 * wz0, c3 = w11 * wz1;

    float* p0 = out + (size_t)b * G3 + ((size_t)bx * G + by) * G + bz;
    float* p1 = p0 + G;
    float* p2 = p0 + G2;
    float* p3 = p2 + G;

    const int off = bz & 3;
    if (off == 3) {
        // Pair straddles a 16B window: 2 scalar reds per corner.
        atomicAdd(p0, a0); atomicAdd(p0 + 1, c0);
        atomicAdd(p1, a1); atomicAdd(p1 + 1, c1);
        atomicAdd(p2, a2); atomicAdd(p2 + 1, c2);
        atomicAdd(p3, a3); atomicAdd(p3 + 1, c3);
    } else if (off == 1) {
        // Odd start inside the window: one v4 with zero padding.
        red4(p0 - 1, 0.f, a0, c0, 0.f);
        red4(p1 - 1, 0.f, a1, c1, 0.f);
        red4(p2 - 1, 0.f, a2, c2, 0.f);
        red4(p3 - 1, 0.f, a3, c3, 0.f);
    } else {
        // bz even: naturally 8B-aligned pair, one v2.
        red2(p0, a0, c0);
        red2(p1, a1, c1);
        red2(p2, a2, c2);
        red2(p3, a3, c3);
    }
}

static const int kChunks = 8;

extern "C" void kernel_launch(void* const* d_in, const int* in_sizes, int n_in,
                              void* d_out, int out_size) {
    const float* pts = (const float*)d_in[0];
    const int* scale_p = (const int*)d_in[1];
    float* out = (float*)d_out;

    const int npts = in_sizes[0] / 3;

    // One-time creation of helper streams + events (no device memory).
    static cudaStream_t sZ = nullptr;   // zeroing stream
    static cudaStream_t sS = nullptr;   // second scatter stream (odd chunks)
    static cudaEvent_t evFork = nullptr;
    static cudaEvent_t evZ[kChunks];
    static cudaEvent_t evS[kChunks];
    if (sZ == nullptr) {
        cudaStreamCreateWithFlags(&sZ, cudaStreamNonBlocking);
        cudaStreamCreateWithFlags(&sS, cudaStreamNonBlocking);
        cudaEventCreateWithFlags(&evFork, cudaEventDisableTiming);
        for (int c = 0; c < kChunks; c++) {
            cudaEventCreateWithFlags(&evZ[c], cudaEventDisableTiming);
            cudaEventCreateWithFlags(&evS[c], cudaEventDisableTiming);
        }
    }

    const int threads = 256;
    int blocksZ = (out_size / kChunks / 4 + threads - 1) / threads;
    if (blocksZ > 2048) blocksZ = 2048;
    if (blocksZ < 1) blocksZ = 1;
    // One point per thread; +2 blocks of slack for chunk-boundary rounding.
    int blocksS = (npts / kChunks + threads - 1) / threads + 2;

    // Fork side streams off the capture stream.
    cudaEventRecord(evFork, 0);
    cudaStreamWaitEvent(sZ, evFork, 0);
    cudaStreamWaitEvent(sS, evFork, 0);

    for (int c = 0; c < kChunks; c++) {
        // Rate-limit zeros: keep at most ~4 chunks (~128MB) hot in L2 so
        // zeros never gate the scatters.
        if (c >= 4) cudaStreamWaitEvent(sZ, evS[c - 4], 0);

        gridding_zero_chunk<<<blocksZ, threads, 0, sZ>>>(
            out, scale_p, out_size, npts, c, kChunks);
        cudaEventRecord(evZ[c], sZ);

        // Scatter chunk c once its zeros are in L2; alternate streams so
        // consecutive chunks' scatters overlap back-to-back.
        cudaStream_t st = (c & 1) ? sS : (cudaStream_t)0;
        cudaStreamWaitEvent(st, evZ[c], 0);
        gridding_scatter_chunk<<<blocksS, threads, 0, st>>>(
            pts, scale_p, out, npts, out_size, c, kChunks);
        cudaEventRecord(evS[c], st);
    }

    // Join everything back into the capture stream.
    cudaStreamWaitEvent(0, evS[kChunks - 1], 0);
}

// round 8
// speedup vs baseline: 1.2804x; 1.0306x over previous
#include <cuda_runtime.h>
#include <cuda_bf16.h>

// Trilinear scatter-add (Gridding).
// L2-resident chunked zero+scatter pipeline + vector reductions.
//
// Converged findings (R1-R6):
//  - Bottleneck: chip-shared L2/LTS throughput (atomic ALU + zero stores).
//    reds ~94us + zero stores ~24us of LTS time -> ~103us roofline.
//  - bz%4 encoding (v2 / padded-v4 / 2x scalar) is op-minimal: 5 ops/pt.
//  - 8 chunks, 1 pt/thread grid-stride, 256-thr blocks, rate-limit 3 is the
//    proven operating point (R3 = 102.9us). 16 chunks / 2pt/thr regressed.
//  - This round: zero stream at LOW priority so zero warps yield SM slots
//    to co-resident scatter blocks (rate-limit slack covers zero delay).
//
// All shape parameters derived on-device from scale/out_size.

__device__ __forceinline__ void get_dims(const int* __restrict__ scale_p,
                                         int out_size, int npts,
                                         int& s, int& G, int& G2, int& G3,
                                         int& B, int& N) {
    const int scale = *scale_p;
    s = scale >> 1;
    G = 2 * s;
    G2 = G * G;
    G3 = G2 * G;
    B = out_size / G3;
    N = npts / B;
}

__device__ __forceinline__ void red2(float* p, float a, float b) {
    asm volatile("red.global.add.v2.f32 [%0], {%1, %2};"
                 :: "l"(p), "f"(a), "f"(b) : "memory");
}

__device__ __forceinline__ void red4(float* p, float a, float b, float c, float d) {
    asm volatile("red.global.add.v4.f32 [%0], {%1, %2, %3, %4};"
                 :: "l"(p), "f"(a), "f"(b), "f"(c), "f"(d) : "memory");
}

// Zero batches [c*B/C, (c+1)*B/C) of the output with float4 stores.
__global__ void gridding_zero_chunk(float* __restrict__ out,
                                    const int* __restrict__ scale_p,
                                    int out_size, int npts, int c, int C) {
    int s, G, G2, G3, B, N;
    get_dims(scale_p, out_size, npts, s, G, G2, G3, B, N);

    const int b0 = (int)((long long)c * B / C);
    const int b1 = (int)((long long)(c + 1) * B / C);
    const size_t lo4 = (size_t)b0 * G3 / 4;   // G even -> G3 % 4 == 0
    const size_t hi4 = (size_t)b1 * G3 / 4;

    float4* o4 = reinterpret_cast<float4*>(out);
    const float4 z = make_float4(0.f, 0.f, 0.f, 0.f);
    const size_t stride = (size_t)gridDim.x * blockDim.x;
    for (size_t i = lo4 + (size_t)blockIdx.x * blockDim.x + threadIdx.x;
         i < hi4; i += stride) {
        o4[i] = z;
    }
}

// Scatter the points of batches [c*B/C, (c+1)*B/C).
__global__ void gridding_scatter_chunk(const float* __restrict__ pts,
                                       const int* __restrict__ scale_p,
                                       float* __restrict__ out,
                                       int npts, int out_size, int c, int C) {
    int s, G, G2, G3, B, N;
    get_dims(scale_p, out_size, npts, s, G, G2, G3, B, N);

    const int b0 = (int)((long long)c * B / C);
    const int b1 = (int)((long long)(c + 1) * B / C);
    const int i_lo = b0 * N;
    const int i_hi = b1 * N;

    const float fs = (float)s;
    const int stride = gridDim.x * blockDim.x;

    for (int i = i_lo + blockIdx.x * blockDim.x + threadIdx.x;
         i < i_hi; i += stride) {
        const int b = b0 + (i - i_lo) / N;

        const float px = pts[3 * i + 0] * fs;
        const float py = pts[3 * i + 1] * fs;
        const float pz = pts[3 * i + 2] * fs;

        // Reference drops points whose scaled coords sum to exactly 0.
        const float m = (((px + py) + pz) != 0.0f) ? 1.0f : 0.0f;

        const float lx = floorf(px);
        const float ly = floorf(py);
        const float lz = floorf(pz);
        const float fx = px - lx;
        const float fy = py - ly;
        const float fz = pz - lz;

        const int bx = (int)lx + s;
        const int by = (int)ly + s;
        const int bz = (int)lz + s;

        const float wx0 = (1.0f - fx) * m;
        const float wx1 = fx * m;
        const float wy0 = 1.0f - fy;
        const float wy1 = fy;
        const float wz0 = 1.0f - fz;
        const float wz1 = fz;

        const float w00 = wx0 * wy0;
        const float w01 = wx0 * wy1;
        const float w10 = wx1 * wy0;
        const float w11 = wx1 * wy1;

        const float a0 = w00 * wz0, c0 = w00 * wz1;
        const float a1 = w01 * wz0, c1 = w01 * wz1;
        const float a2 = w10 * wz0, c2 = w10 * wz1;
        const float a3 = w11 * wz0, c3 = w11 * wz1;

        float* p0 = out + (size_t)b * G3 + ((size_t)bx * G + by) * G + bz;
        float* p1 = p0 + G;
        float* p2 = p0 + G2;
        float* p3 = p2 + G;

        const int off = bz & 3;
        if (off == 3) {
            // Pair straddles a 16B window: 2 scalar reds per corner.
            atomicAdd(p0, a0); atomicAdd(p0 + 1, c0);
            atomicAdd(p1, a1); atomicAdd(p1 + 1, c1);
            atomicAdd(p2, a2); atomicAdd(p2 + 1, c2);
            atomicAdd(p3, a3); atomicAdd(p3 + 1, c3);
        } else if (off == 1) {
            // Odd start inside the window: one v4 with zero padding.
            red4(p0 - 1, 0.f, a0, c0, 0.f);
            red4(p1 - 1, 0.f, a1, c1, 0.f);
            red4(p2 - 1, 0.f, a2, c2, 0.f);
            red4(p3 - 1, 0.f, a3, c3, 0.f);
        } else {
            // bz even: naturally 8B-aligned pair, one v2.
            red2(p0, a0, c0);
            red2(p1, a1, c1);
            red2(p2, a2, c2);
            red2(p3, a3, c3);
        }
    }
}

static const int kChunks = 8;

extern "C" void kernel_launch(void* const* d_in, const int* in_sizes, int n_in,
                              void* d_out, int out_size) {
    const float* pts = (const float*)d_in[0];
    const int* scale_p = (const int*)d_in[1];
    float* out = (float*)d_out;

    const int npts = in_sizes[0] / 3;

    // One-time creation of helper streams + events (no device memory).
    static cudaStream_t sZ = nullptr;   // zeroing stream (low priority)
    static cudaStream_t sS = nullptr;   // second scatter stream (odd chunks)
    static cudaEvent_t evFork = nullptr;
    static cudaEvent_t evZ[kChunks];
    static cudaEvent_t evS[kChunks];
    if (sZ == nullptr) {
        int prLo = 0, prHi = 0;
        cudaDeviceGetStreamPriorityRange(&prLo, &prHi);  // prLo = lowest prio
        cudaStreamCreateWithPriority(&sZ, cudaStreamNonBlocking, prLo);
        cudaStreamCreateWithFlags(&sS, cudaStreamNonBlocking);
        cudaEventCreateWithFlags(&evFork, cudaEventDisableTiming);
        for (int c = 0; c < kChunks; c++) {
            cudaEventCreateWithFlags(&evZ[c], cudaEventDisableTiming);
            cudaEventCreateWithFlags(&evS[c], cudaEventDisableTiming);
        }
    }

    const int threads = 256;
    int blocksZ = (out_size / kChunks / 4 + threads - 1) / threads;
    if (blocksZ > 2048) blocksZ = 2048;
    if (blocksZ < 1) blocksZ = 1;
    int blocksS = (npts / kChunks + threads - 1) / threads + 2;

    // Fork side streams off the capture stream.
    cudaEventRecord(evFork, 0);
    cudaStreamWaitEvent(sZ, evFork, 0);
    cudaStreamWaitEvent(sS, evFork, 0);

    for (int c = 0; c < kChunks; c++) {
        // Rate-limit zeros: keep at most ~3 chunks hot in L2.
        if (c >= 3) cudaStreamWaitEvent(sZ, evS[c - 3], 0);

        gridding_zero_chunk<<<blocksZ, threads, 0, sZ>>>(
            out, scale_p, out_size, npts, c, kChunks);
        cudaEventRecord(evZ[c], sZ);

        // Scatter chunk c once its zeros are in L2. Even chunks on the
        // capture stream, odd chunks on the second stream.
        cudaStream_t st = (c & 1) ? sS : (cudaStream_t)0;
        cudaStreamWaitEvent(st, evZ[c], 0);
        gridding_scatter_chunk<<<blocksS, threads, 0, st>>>(
            pts, scale_p, out, npts, out_size, c, kChunks);
        cudaEventRecord(evS[c], st);
    }

    // Join everything back into the capture stream.
    cudaStreamWaitEvent(0, evS[kChunks - 1], 0);
}